// round 16
// baseline (speedup 1.0000x reference)
#include <cuda_runtime.h>
#include <cuda_bf16.h>
#include <cstdint>

// Problem constants (fixed by the dataset)
#define MAXN 50000
#define CAP  128      // max in-degree capacity (Poisson(16): P(deg>=128) ~ 0)

// Scratch (device globals: allocation-free per harness rules)
__device__ __align__(128) int   g_cnt[MAXN];                // in-degree
__device__ __align__(128) int   g_slot[(size_t)MAXN * CAP]; // bucketed src per dst
__device__ __align__(128) float g_z  [(size_t)MAXN * 128];  // z  = x @ W1
__device__ __align__(128) float g_t  [(size_t)MAXN * 16];   // t  = h2 @ W2
__device__ __align__(128) __nv_bfloat16 g_wh[128 * 128];    // W1^T hi  [nc][k]
__device__ __align__(128) __nv_bfloat16 g_wl[128 * 128];    // W1^T lo  [nc][k]
__device__ int g_is64;                                      // edge dtype flag

// ---------------------------------------------------------------------------
__device__ __forceinline__ uint32_t smem_to_u32(const void* p) {
    uint32_t a;
    asm("{ .reg .u64 t; cvta.to.shared.u64 t, %1; cvt.u32.u64 %0, t; }"
        : "=r"(a) : "l"(p));
    return a;
}

// Portable tensor-core primitives (sm_80+; valid on base compute_103 target)
#define LDSM_X4(r, addr) \
    asm volatile("ldmatrix.sync.aligned.m8n8.x4.shared.b16 {%0,%1,%2,%3}, [%4];" \
        : "=r"((r)[0]), "=r"((r)[1]), "=r"((r)[2]), "=r"((r)[3]) : "r"(addr))

#define MMA_BF16(d, a, b) \
    asm volatile("mma.sync.aligned.m16n8k16.row.col.f32.bf16.bf16.f32 " \
        "{%0,%1,%2,%3}, {%4,%5,%6,%7}, {%8,%9}, {%0,%1,%2,%3};" \
        : "+f"((d)[0]), "+f"((d)[1]), "+f"((d)[2]), "+f"((d)[3]) \
        : "r"((a)[0]), "r"((a)[1]), "r"((a)[2]), "r"((a)[3]), \
          "r"((b)[0]), "r"((b)[1]))

// ---------------------------------------------------------------------------
// Setup: zero g_cnt, split W1 -> g_wh/g_wl, probe edge dtype (block 0, ordered)
__global__ void setup_kernel(const float* __restrict__ W,
                             const void* __restrict__ ei, int E, int n) {
    const int tid = threadIdx.x;
    const int gid = blockIdx.x * blockDim.x + tid;

    if (blockIdx.x == 0) {
        if (tid == 0) g_is64 = 1;
        __syncthreads();
        const long long* e64 = (const long long*)ei;
        int m = min(128, E);
        if (tid < m) {
            long long v = e64[tid];   // within allocation for either dtype
            if (v < 0 || v >= (long long)n) atomicAnd(&g_is64, 0);
        }
    }
    // zero in-degree counters
    for (int i = gid; i < n; i += gridDim.x * blockDim.x)
        g_cnt[i] = 0;
    // W1 split: g_wh/g_wl[nc][k] = split_bf16(W1[k][nc])
    for (int i = gid; i < 128 * 128; i += gridDim.x * blockDim.x) {
        int nc = i & 127;
        float f = W[i];                      // W[k*128 + nc], coalesced
        __nv_bfloat16 h = __float2bfloat16(f);
        g_wh[nc * 128 + (i >> 7)] = h;
        g_wl[nc * 128 + (i >> 7)] = __float2bfloat16(f - __bfloat162float(h));
    }
}

// ============================================================================
// GEMM1 (HMMA) + fused edge-build prologue.  (unchanged from R12)
// ============================================================================
#define XS 136
#define TILE_ELEMS (128 * XS)
#define G1_SMEM_TOTAL (4 * TILE_ELEMS * 2)   // Xh, Xl, Bh, Bl = 139264 B

__global__ void __launch_bounds__(512, 1)
gemm1_build_kernel(const float* __restrict__ X,
                   const void* __restrict__ ei, int E, int n) {
    extern __shared__ __align__(16) char smem_raw[];
    __nv_bfloat16* Xh = (__nv_bfloat16*)smem_raw;       // [128][XS] row=m, col=k
    __nv_bfloat16* Xl = Xh + TILE_ELEMS;
    __nv_bfloat16* Bh = Xl + TILE_ELEMS;                // [128][XS] row=n, col=k
    __nv_bfloat16* Bl = Bh + TILE_ELEMS;

    const int tid  = threadIdx.x;
    const int wid  = tid >> 5;
    const int lane = tid & 31;
    const int row0 = blockIdx.x * 128;

    // ---- build prologue: this block's edge chunk (independent of GEMM) ----
    {
        const int nb  = gridDim.x;
        const int per = (E + nb - 1) / nb;
        const int e0  = blockIdx.x * per;
        const int e1  = min(E, e0 + per);
        const int isw = g_is64;
        for (int e = e0 + tid; e < e1; e += 512) {
            int s, d;
            if (isw) {
                const long long* e64 = (const long long*)ei;
                s = (int)e64[e];
                d = (int)e64[(size_t)E + e];
            } else {
                const int* e32 = (const int*)ei;
                s = e32[e];
                d = e32[(size_t)E + e];
            }
            if (d >= 0 && d < n && s >= 0 && s < n) {
                int pos = atomicAdd(&g_cnt[d], 1);
                if (pos < CAP) g_slot[(size_t)d * CAP + pos] = s;
            }
        }
    }

    // ---- stage + split-convert X tile: thread -> (row, k-quarter) ----
    {
        const int r = tid >> 2, q = tid & 3;
        int gr = row0 + r; if (gr >= n) gr = n - 1;   // clamp; stores guarded later
        const float* xp = X + (size_t)gr * 128 + q * 32;
        __nv_bfloat16* ph = Xh + r * XS + q * 32;
        __nv_bfloat16* pl = Xl + r * XS + q * 32;
#pragma unroll
        for (int j = 0; j < 32; j += 4) {
            float4 v = *(const float4*)(xp + j);
            float fv[4] = {v.x, v.y, v.z, v.w};
#pragma unroll
            for (int e = 0; e < 4; e++) {
                __nv_bfloat16 h = __float2bfloat16(fv[e]);
                __nv_bfloat16 l = __float2bfloat16(fv[e] - __bfloat162float(h));
                ph[j + e] = h;
                pl[j + e] = l;
            }
        }
    }
    // ---- stage B tiles: straight uint4 copy from pre-split g_wh/g_wl ----
    {
#pragma unroll
        for (int it = 0; it < 4; it++) {
            int idx = tid + it * 512;          // 0..2047 : row = idx>>4, 16B chunk
            int row = idx >> 4, c16 = idx & 15;
            ((uint4*)(Bh + row * XS))[c16] = ((const uint4*)(g_wh + row * 128))[c16];
            ((uint4*)(Bl + row * XS))[c16] = ((const uint4*)(g_wl + row * 128))[c16];
        }
    }
    __syncthreads();

    // ---- warp tile: rows strip rs = (wid>>1)*16, col half ch = wid&1 ----
    const int rs = (wid >> 1) * 16;
    const int ch = wid & 1;

    float acc[8][4];
#pragma unroll
    for (int nf = 0; nf < 8; nf++)
#pragma unroll
        for (int c = 0; c < 4; c++) acc[nf][c] = 0.f;

    const int a_row  = rs + ((lane >> 3) & 1) * 8 + (lane & 7);
    const int a_koff = (lane >> 4) * 8;
    const uint32_t a_hi_base = smem_to_u32(Xh + a_row * XS + a_koff);
    const uint32_t a_lo_base = smem_to_u32(Xl + a_row * XS + a_koff);

    // Fused B ldmatrix.x4: lanes 0-15 -> Bh (k0/k8), lanes 16-31 -> Bl.
    {
        const __nv_bfloat16* barr = (lane & 16) ? Bl : Bh;
        const int b_row  = ch * 64 + (lane & 7);
        const int b_koff = ((lane >> 3) & 1) * 8;
        const uint32_t b_base = smem_to_u32(barr + b_row * XS + b_koff);

#pragma unroll
        for (int k = 0; k < 8; k++) {
            uint32_t ah[4], al[4];
            LDSM_X4(ah, a_hi_base + k * 32);   // 16 bf16 = 32B per k-step
            LDSM_X4(al, a_lo_base + k * 32);
#pragma unroll
            for (int nf = 0; nf < 8; nf++) {
                uint32_t bb[4];
                LDSM_X4(bb, b_base + nf * (8 * XS * 2) + k * 32);
                MMA_BF16(acc[nf], ah, bb + 0);   // Ah * Bh
                MMA_BF16(acc[nf], ah, bb + 2);   // Ah * Bl
                MMA_BF16(acc[nf], al, bb + 0);   // Al * Bh
            }
        }
    }

    // ---- epilogue: c0,c1 -> (row, col..col+1); c2,c3 -> (row+8, ..) ----
    {
        const int row_lo = row0 + rs + (lane >> 2);
        const int colb   = ch * 64 + (lane & 3) * 2;
#pragma unroll
        for (int nf = 0; nf < 8; nf++) {
            int c = colb + nf * 8;
            if (row_lo < n)
                *(float2*)(g_z + (size_t)row_lo * 128 + c) =
                    make_float2(acc[nf][0], acc[nf][1]);
            if (row_lo + 8 < n)
                *(float2*)(g_z + (size_t)(row_lo + 8) * 128 + c) =
                    make_float2(acc[nf][2], acc[nf][3]);
        }
    }
}

// ---------------------------------------------------------------------------
// Gather1 + fused GEMM2 (8-way MLP in the edge loop):
//   h2 = relu(mean_{s in nbr(i)} z[s] + b1) * mask[i]   (held in registers)
//   t[i] = h2 @ W2   (per-warp smem staging, 16 cols)
__global__ __launch_bounds__(256) void gather1_fused_kernel(
    const float* __restrict__ b1, const float* __restrict__ mask,
    const float* __restrict__ W2, int n) {
    __shared__ float W2s[128 * 16];
    __shared__ float h2s[8][128];

    // cooperative W2 load (before any early-out)
#pragma unroll
    for (int j = 0; j < 8; j++)
        W2s[threadIdx.x + j * 256] = W2[threadIdx.x + j * 256];
    __syncthreads();

    const int warp  = (blockIdx.x * blockDim.x + threadIdx.x) >> 5;
    const int lane  = threadIdx.x & 31;
    const int wslot = (threadIdx.x >> 5);
    if (warp >= n) return;

    const int deg = g_cnt[warp];
    const int d   = min(deg, CAP);
    const int* sl = g_slot + (size_t)warp * CAP;
    float4 acc = make_float4(0.f, 0.f, 0.f, 0.f);

    for (int base = 0; base < d; base += 32) {
        int nn = min(32, d - base);
        int my = (lane < nn) ? sl[base + lane] : 0;
        int e = 0;
        for (; e + 8 <= nn; e += 8) {   // 8-way MLP
            int s0 = __shfl_sync(0xffffffffu, my, e + 0);
            int s1 = __shfl_sync(0xffffffffu, my, e + 1);
            int s2 = __shfl_sync(0xffffffffu, my, e + 2);
            int s3 = __shfl_sync(0xffffffffu, my, e + 3);
            int s4 = __shfl_sync(0xffffffffu, my, e + 4);
            int s5 = __shfl_sync(0xffffffffu, my, e + 5);
            int s6 = __shfl_sync(0xffffffffu, my, e + 6);
            int s7 = __shfl_sync(0xffffffffu, my, e + 7);
            float4 v0 = *(const float4*)(g_z + (size_t)s0 * 128 + lane * 4);
            float4 v1 = *(const float4*)(g_z + (size_t)s1 * 128 + lane * 4);
            float4 v2 = *(const float4*)(g_z + (size_t)s2 * 128 + lane * 4);
            float4 v3 = *(const float4*)(g_z + (size_t)s3 * 128 + lane * 4);
            float4 v4 = *(const float4*)(g_z + (size_t)s4 * 128 + lane * 4);
            float4 v5 = *(const float4*)(g_z + (size_t)s5 * 128 + lane * 4);
            float4 v6 = *(const float4*)(g_z + (size_t)s6 * 128 + lane * 4);
            float4 v7 = *(const float4*)(g_z + (size_t)s7 * 128 + lane * 4);
            acc.x += (v0.x + v1.x + v2.x + v3.x) + (v4.x + v5.x + v6.x + v7.x);
            acc.y += (v0.y + v1.y + v2.y + v3.y) + (v4.y + v5.y + v6.y + v7.y);
            acc.z += (v0.z + v1.z + v2.z + v3.z) + (v4.z + v5.z + v6.z + v7.z);
            acc.w += (v0.w + v1.w + v2.w + v3.w) + (v4.w + v5.w + v6.w + v7.w);
        }
        for (; e + 4 <= nn; e += 4) {
            int s0 = __shfl_sync(0xffffffffu, my, e + 0);
            int s1 = __shfl_sync(0xffffffffu, my, e + 1);
            int s2 = __shfl_sync(0xffffffffu, my, e + 2);
            int s3 = __shfl_sync(0xffffffffu, my, e + 3);
            float4 v0 = *(const float4*)(g_z + (size_t)s0 * 128 + lane * 4);
            float4 v1 = *(const float4*)(g_z + (size_t)s1 * 128 + lane * 4);
            float4 v2 = *(const float4*)(g_z + (size_t)s2 * 128 + lane * 4);
            float4 v3 = *(const float4*)(g_z + (size_t)s3 * 128 + lane * 4);
            acc.x += v0.x + v1.x + v2.x + v3.x;
            acc.y += v0.y + v1.y + v2.y + v3.y;
            acc.z += v0.z + v1.z + v2.z + v3.z;
            acc.w += v0.w + v1.w + v2.w + v3.w;
        }
        for (; e < nn; e++) {
            int s = __shfl_sync(0xffffffffu, my, e);
            float4 v = *(const float4*)(g_z + (size_t)s * 128 + lane * 4);
            acc.x += v.x; acc.y += v.y; acc.z += v.z; acc.w += v.w;
        }
    }
    float scale = 1.f / (float)max(deg, 1);
    float bb0 = b1[lane * 4 + 0], bb1 = b1[lane * 4 + 1];
    float bb2 = b1[lane * 4 + 2], bb3 = b1[lane * 4 + 3];
    const float* mp = mask + (size_t)warp * 128 + lane * 4;
    float m0 = mp[0], m1 = mp[1], m2 = mp[2], m3 = mp[3];
    float4 r;
    r.x = fmaxf(fmaf(acc.x, scale, bb0), 0.f) * m0;
    r.y = fmaxf(fmaf(acc.y, scale, bb1), 0.f) * m1;
    r.z = fmaxf(fmaf(acc.z, scale, bb2), 0.f) * m2;
    r.w = fmaxf(fmaf(acc.w, scale, bb3), 0.f) * m3;

    // ---- fused gemm2: t[c] = sum_k h2[k] * W2[k][c] ----
    float* hb = h2s[wslot];
    *(float4*)(hb + lane * 4) = r;
    __syncwarp();

    const int c     = lane & 15;
    const int kbase = (lane >> 4) * 64;       // lanes 0-15: k 0..63; 16-31: 64..127
    float p = 0.f;
#pragma unroll 16
    for (int j = 0; j < 64; j++)
        p = fmaf(hb[kbase + j], W2s[(kbase + j) * 16 + c], p);
    p += __shfl_xor_sync(0xffffffffu, p, 16);
    if (lane < 16) g_t[(size_t)warp * 16 + c] = p;
}

// ---------------------------------------------------------------------------
// Gather2 (warp-per-node): out[i] = mean_{s in nbr(i)} t[s] + b2
//   lane = (edge-slot 0-7, quarter 0-3): 32 independent float4 loads per round,
//   shfl_xor(4/8/16) reduces edge slots; lanes 0-3 write 4 floats each.
__global__ __launch_bounds__(256) void gather2_kernel(
    const float* __restrict__ b2, float* __restrict__ out, int n) {
    const int node = (blockIdx.x * blockDim.x + threadIdx.x) >> 5;
    const int lane = threadIdx.x & 31;
    if (node >= n) return;

    const int eq = lane >> 2;         // edge slot 0..7
    const int q  = (lane & 3) * 4;    // float4 quarter

    const int deg = g_cnt[node];
    const int d   = min(deg, CAP);
    const int* sl = g_slot + (size_t)node * CAP;
    float4 acc = make_float4(0.f, 0.f, 0.f, 0.f);

    for (int base = 0; base < d; base += 8) {
        int e = base + eq;
        if (e < d) {
            int s = sl[e];
            float4 v = *(const float4*)(g_t + (size_t)s * 16 + q);
            acc.x += v.x; acc.y += v.y; acc.z += v.z; acc.w += v.w;
        }
    }
    // reduce across edge slots (lanes with equal lane&3)
#pragma unroll
    for (int off = 4; off < 32; off <<= 1) {
        acc.x += __shfl_xor_sync(0xffffffffu, acc.x, off);
        acc.y += __shfl_xor_sync(0xffffffffu, acc.y, off);
        acc.z += __shfl_xor_sync(0xffffffffu, acc.z, off);
        acc.w += __shfl_xor_sync(0xffffffffu, acc.w, off);
    }
    if (lane < 4) {
        float scale = 1.f / (float)max(deg, 1);
        out[(size_t)node * 16 + q + 0] = fmaf(acc.x, scale, b2[q + 0]);
        out[(size_t)node * 16 + q + 1] = fmaf(acc.y, scale, b2[q + 1]);
        out[(size_t)node * 16 + q + 2] = fmaf(acc.z, scale, b2[q + 2]);
        out[(size_t)node * 16 + q + 3] = fmaf(acc.w, scale, b2[q + 3]);
    }
}

// ---------------------------------------------------------------------------
extern "C" void kernel_launch(void* const* d_in, const int* in_sizes, int n_in,
                              void* d_out, int out_size) {
    const float* x    = (const float*)d_in[0];
    const void*  ei   = d_in[1];            // int32 or int64, probed on device
    const float* W1   = (const float*)d_in[2];
    const float* b1   = (const float*)d_in[3];
    const float* W2   = (const float*)d_in[4];
    const float* b2   = (const float*)d_in[5];
    const float* mask = (const float*)d_in[6];
    float*       out  = (float*)d_out;

    int n = in_sizes[0] / 128;
    if (n > MAXN) n = MAXN;
    int E = in_sizes[1] / 2;

    // idempotent; persists on the function after the first (pre-capture) call
    cudaFuncSetAttribute(gemm1_build_kernel,
                         cudaFuncAttributeMaxDynamicSharedMemorySize,
                         G1_SMEM_TOTAL);

    setup_kernel<<<196, 256>>>(W1, ei, E, n);
    gemm1_build_kernel<<<(n + 127) / 128, 512, G1_SMEM_TOTAL>>>(x, ei, E, n);
    gather1_fused_kernel<<<(n + 7) / 8, 256>>>(b1, mask, W2, n);
    gather2_kernel<<<(n + 7) / 8, 256>>>(b2, out, n);
}